// round 9
// baseline (speedup 1.0000x reference)
#include <cuda_runtime.h>
#include <cuda_bf16.h>

// Segment-sum scatter at the LTS/atomic structural floor (~50us kernel),
// with PDL (programmatic dependent launch) hiding the output-zeroing under
// the scatter kernel's load phase.
//
// Confirmed floor model (R1/R3/R6/R7 at 50.0-50.9us; all deviations 70us+):
// the L2/atomic subsystem binds — 218MB read-fill + 205MB RED payload through
// the crossbar plus slice-internal RMW traffic. Bytes/ops irreducible (16B max
// RED width, bf16 fails 1e-3, no duplicates to aggregate on uniform-random
// indices, per-replay zeroing mandatory).
//
// New in R8: the remaining ~3.7us of total-vs-kernel gap is node overhead.
// The zero->scatter dependency is only needed before the FIRST RED, not before
// the loads. So: zero kernel triggers PDL completion at entry; scatter kernel
// launches early (programmatic serialization), front-batches its 8 loads, then
// cudaGridDependencySynchronize() before the REDs. If capture serializes the
// edge instead, the sync is a no-op and behavior matches R7.
//
// Fixed sizes: E = 3,200,000, F = 16 -> 12.8M quads = 3.2M threads x 4.
// Output: 1.6M floats = 400,000 float4.

#define E_TOTAL   3200000
#define NUM_QUADS (E_TOTAL * 4)
#define TPB       256
#define QPT       4
#define TOTAL_THREADS (NUM_QUADS / QPT)        // 3,200,000
#define NBLK          (TOTAL_THREADS / TPB)    // 12,500

#define OUT_F4    400000
#define ZTPB      256
#define ZBLK      ((OUT_F4 + ZTPB - 1) / ZTPB) // 1563

__global__ void __launch_bounds__(ZTPB)
zero_out_kernel(float4* __restrict__ out4)
{
#if __CUDA_ARCH__ >= 900
    // Allow the dependent scatter kernel to begin its load phase immediately.
    cudaTriggerProgrammaticLaunchCompletion();
#endif
    int i = blockIdx.x * ZTPB + threadIdx.x;
    if (i < OUT_F4)
        out4[i] = make_float4(0.f, 0.f, 0.f, 0.f);
}

__global__ void __launch_bounds__(TPB)
spmm_scatter_kernel(const int* __restrict__ src,
                    const float4* __restrict__ w4,   // [E*4] float4
                    float4* __restrict__ out4)       // [N*4] float4
{
    const int tid = blockIdx.x * TPB + threadIdx.x;
    const int S   = TOTAL_THREADS;

    const int i0 = tid;
    const int i1 = tid + S;
    const int i2 = tid + 2 * S;
    const int i3 = tid + 3 * S;

    // Front-batched independent loads (MLP ~8) — these do NOT touch out4,
    // so they legally overlap the still-running zero kernel under PDL.
    int s0 = __ldg(&src[i0 >> 2]);
    int s1 = __ldg(&src[i1 >> 2]);
    int s2 = __ldg(&src[i2 >> 2]);
    int s3 = __ldg(&src[i3 >> 2]);

    float4 v0 = __ldcs(&w4[i0]);   // evict-first: edge_w streams once,
    float4 v1 = __ldcs(&w4[i1]);   // keep L2 for the atomic destinations
    float4 v2 = __ldcs(&w4[i2]);
    float4 v3 = __ldcs(&w4[i3]);

#if __CUDA_ARCH__ >= 900
    // Wait for the zero kernel's writes to be complete/visible before RMW.
    cudaGridDependencySynchronize();
#endif

    atomicAdd(&out4[((size_t)s0 << 2) + (i0 & 3)], v0);
    atomicAdd(&out4[((size_t)s1 << 2) + (i1 & 3)], v1);
    atomicAdd(&out4[((size_t)s2 << 2) + (i2 & 3)], v2);
    atomicAdd(&out4[((size_t)s3 << 2) + (i3 & 3)], v3);
}

extern "C" void kernel_launch(void* const* d_in, const int* in_sizes, int n_in,
                              void* d_out, int out_size)
{
    const int*   edge   = (const int*)d_in[0];   // edge[0] = src, first E ints
    const float* edge_w = (const float*)d_in[1];
    float4*      out4   = (float4*)d_out;

    // Zero kernel (replaces memset; triggers PDL completion at entry).
    zero_out_kernel<<<ZBLK, ZTPB>>>(out4);

    // Scatter kernel launched with programmatic stream serialization so it
    // can begin its load phase while the zero kernel drains.
    cudaLaunchConfig_t cfg = {};
    cfg.gridDim  = dim3(NBLK, 1, 1);
    cfg.blockDim = dim3(TPB, 1, 1);
    cfg.dynamicSmemBytes = 0;
    cfg.stream = 0;

    cudaLaunchAttribute attr[1];
    attr[0].id = cudaLaunchAttributeProgrammaticStreamSerialization;
    attr[0].val.programmaticStreamSerializationAllowed = 1;
    cfg.attrs = attr;
    cfg.numAttrs = 1;

    cudaLaunchKernelEx(&cfg, spmm_scatter_kernel,
                       (const int*)edge,
                       (const float4*)edge_w,
                       out4);
}

// round 10
// speedup vs baseline: 1.0006x; 1.0006x over previous
#include <cuda_runtime.h>
#include <cuda_bf16.h>

// FINAL: segment-sum scatter at the LTS/atomic structural floor.
//
// Floor model (confirmed 4x at 50.0-50.9us kernel; every deviation regressed):
// the L2 subsystem binds — 218MB read-fill + 205MB RED.E.ADD.F32.V4 payload
// through the crossbar plus slice-internal RMW traffic saturate the LTS
// (~6300 B/cyc path-independent cap + atomic-ALU slots) while every SM-side
// metric stays slack (issue 10%, DRAM 57%, occ 83%).
//
// Levers ruled out by measurement:
//   TPB=512           -> L1tex-queue contention, +37%  (R5)
//   per-edge 64B loads-> coalescing break,       +60%  (R2)
//   TMA bulk-reduce   -> ALU/TMA envelope cost,  +40%  (R4)
//   PDL zero overlap  -> contends w/ saturated LTS, net 0  (R8)
//   bf16 payload      -> fails 1e-3 rel-err budget
//   dedup/aggregation -> ~0 expected duplicates (uniform-random indices)
//
// Proven-optimal shape: TPB=256, 4 quads/thread grid-strided by the total
// thread count. Warp loads 32 consecutive float4s = 4 x 128B lines/LDG.128;
// 4 lanes share one broadcast src int; 8 loads front-batched (MLP_p1=8) ahead
// of 4 fire-and-forget REDs (each edge's 4 lanes cover one contiguous 64B
// output line). edge_w streams evict-first (__ldcs) so the 6.4MB destination
// region stays L2-resident for the RMWs.
//
// Fixed sizes: E = 3,200,000, F = 16 -> 12.8M quads = 3.2M threads x 4.

#define E_TOTAL   3200000
#define NUM_QUADS (E_TOTAL * 4)
#define TPB       256
#define QPT       4
#define TOTAL_THREADS (NUM_QUADS / QPT)        // 3,200,000
#define NBLK          (TOTAL_THREADS / TPB)    // 12,500

__global__ void __launch_bounds__(TPB)
spmm_scatter_kernel(const int* __restrict__ src,
                    const float4* __restrict__ w4,   // [E*4] float4
                    float4* __restrict__ out4)       // [N*4] float4
{
    const int tid = blockIdx.x * TPB + threadIdx.x;
    const int S   = TOTAL_THREADS;

    const int i0 = tid;
    const int i1 = tid + S;
    const int i2 = tid + 2 * S;
    const int i3 = tid + 3 * S;

    // Front-batched independent loads (ptxas hoists these together, MLP ~8).
    int s0 = __ldg(&src[i0 >> 2]);
    int s1 = __ldg(&src[i1 >> 2]);
    int s2 = __ldg(&src[i2 >> 2]);
    int s3 = __ldg(&src[i3 >> 2]);

    float4 v0 = __ldcs(&w4[i0]);   // evict-first: edge_w streams once,
    float4 v1 = __ldcs(&w4[i1]);   // keep L2 for the atomic destinations
    float4 v2 = __ldcs(&w4[i2]);
    float4 v3 = __ldcs(&w4[i3]);

    atomicAdd(&out4[((size_t)s0 << 2) + (i0 & 3)], v0);
    atomicAdd(&out4[((size_t)s1 << 2) + (i1 & 3)], v1);
    atomicAdd(&out4[((size_t)s2 << 2) + (i2 & 3)], v2);
    atomicAdd(&out4[((size_t)s3 << 2) + (i3 & 3)], v3);
}

extern "C" void kernel_launch(void* const* d_in, const int* in_sizes, int n_in,
                              void* d_out, int out_size)
{
    const int*   edge   = (const int*)d_in[0];   // edge[0] = src, first E ints
    const float* edge_w = (const float*)d_in[1];

    // d_out poisoned to 0xAA -> zero it (memset node is graph-capturable);
    // also pre-warms the 6.4 MB destination region in L2. Mandatory every
    // replay: REDs accumulate otherwise.
    cudaMemsetAsync(d_out, 0, (size_t)out_size * sizeof(float), 0);

    spmm_scatter_kernel<<<NBLK, TPB>>>(
        edge,
        (const float4*)edge_w,
        (float4*)d_out);
}